// round 16
// baseline (speedup 1.0000x reference)
#include <cuda_runtime.h>
#include <cstdint>

#define N_NODES   1048576
#define N_GRAPHS  1024
#define F_X       128
#define F_U       128
#define F_CAT     256
#define HIDDEN    512
#define F_OUT     128

// Scratch (allocation-free rule: __device__ globals)
__device__ float g_concat[N_GRAPHS * F_CAT];   // [1024,256] = x_agg || u
__device__ float g_h[N_GRAPHS * HIDDEN];       // [1024,512]

// ---------------------------------------------------------------------------
// Warp-collective lower_bound on sorted int array: 32-ary search.
// ---------------------------------------------------------------------------
__device__ __forceinline__ int warp_lower_bound(const int* __restrict__ batch,
                                                int target, int lane) {
    int lo = 0, hi = N_NODES;              // answer in [lo, hi]
    while (hi - lo > 32) {
        int step = (hi - lo) >> 5;         // >= 1
        int pos  = lo + lane * step;
        int v    = __ldg(batch + pos);
        unsigned mask = __ballot_sync(0xffffffffu, v < target);
        if (mask == 0) {
            hi = lo + step;
        } else {
            int istar = 31 - __clz(mask);
            int nlo   = lo + istar * step;
            int nhi   = (istar < 31) ? (nlo + step) : hi;
            lo = nlo; hi = nhi;
        }
    }
    int pos = lo + lane;
    int v   = (pos < hi) ? __ldg(batch + pos) : 0x7fffffff;
    unsigned mask = __ballot_sync(0xffffffffu, (pos < hi) && (v < target));
    return lo + __popc(mask);
}

// ---------------------------------------------------------------------------
// 1) Segment mean of x -> g_concat[:,0:128]; u -> g_concat[:,128:256].
//    One block per graph, 256 threads; single wave; at the spr_max floor.
// ---------------------------------------------------------------------------
__global__ void __launch_bounds__(256, 8) seg_mean_kernel(const float* __restrict__ x,
                                                          const float* __restrict__ u,
                                                          const int*   __restrict__ batch) {
    const int g    = blockIdx.x;
    const int tid  = threadIdx.x;
    const int lane = tid & 31;   // feature quad
    const int grp  = tid >> 5;   // row group 0..7

    __shared__ int s_se[2];
    if (grp < 2) {               // warp 0 -> start, warp 1 -> end
        int r = warp_lower_bound(batch, g + grp, lane);
        if (lane == 0) s_se[grp] = r;
    }
    __syncthreads();
    const int start = s_se[0];
    const int end   = s_se[1];

    const float* xb = x + (size_t)lane * 4;

    float4 a0 = {0,0,0,0}, a1 = {0,0,0,0};
    int r = start + grp;
    for (; r + 8 < end; r += 16) {      // 2 loads in flight per thread
        float4 v0 = __ldcs((const float4*)(xb + (size_t)(r    ) * F_X));
        float4 v1 = __ldcs((const float4*)(xb + (size_t)(r + 8) * F_X));
        a0.x += v0.x; a0.y += v0.y; a0.z += v0.z; a0.w += v0.w;
        a1.x += v1.x; a1.y += v1.y; a1.z += v1.z; a1.w += v1.w;
    }
    if (r < end) {
        float4 v = __ldcs((const float4*)(xb + (size_t)r * F_X));
        a0.x += v.x; a0.y += v.y; a0.z += v.z; a0.w += v.w;
    }
    a0.x += a1.x; a0.y += a1.y; a0.z += a1.z; a0.w += a1.w;

    __shared__ float4 sm[8][32];
    sm[grp][lane] = a0;
    __syncthreads();
    #pragma unroll
    for (int s = 4; s > 0; s >>= 1) {
        if (grp < s) {
            float4 a = sm[grp][lane];
            float4 b = sm[grp + s][lane];
            a.x += b.x; a.y += b.y; a.z += b.z; a.w += b.w;
            sm[grp][lane] = a;
        }
        __syncthreads();
    }

    if (grp == 0) {
        int cnt = end - start;
        float inv = (cnt > 0) ? (1.0f / (float)cnt) : 0.0f;
        float4 a = sm[0][lane];
        a.x *= inv; a.y *= inv; a.z *= inv; a.w *= inv;
        *(float4*)(g_concat + (size_t)g * F_CAT + lane * 4) = a;
    } else if (grp == 1) {
        float4 v = *(const float4*)(u + (size_t)g * F_U + lane * 4);
        *(float4*)(g_concat + (size_t)g * F_CAT + F_X + lane * 4) = v;
    }
}

// ---------------------------------------------------------------------------
// tf32 helpers
// ---------------------------------------------------------------------------
__device__ __forceinline__ float to_tf32(float f) {
    uint32_t u;
    asm("cvt.rna.tf32.f32 %0, %1;" : "=r"(u) : "f"(f));
    return __uint_as_float(u);
}

__device__ __forceinline__ void mma_tf32(float d[4],
                                         uint32_t a0, uint32_t a1, uint32_t a2, uint32_t a3,
                                         uint32_t b0, uint32_t b1) {
    asm("mma.sync.aligned.m16n8k8.row.col.f32.tf32.tf32.f32 "
        "{%0,%1,%2,%3}, {%4,%5,%6,%7}, {%8,%9}, {%0,%1,%2,%3};"
        : "+f"(d[0]), "+f"(d[1]), "+f"(d[2]), "+f"(d[3])
        : "r"(a0), "r"(a1), "r"(a2), "r"(a3), "r"(b0), "r"(b1));
}

// ---------------------------------------------------------------------------
// 2) GEMM1 via tf32 tensor cores: h = relu(concat @ W1 + b1).
//    Block = 256 threads (8 warps), 64x64 tile, BK=32; warp grid 4m x 2n.
//    Grid = 8 x 16 = 128 blocks. (R15 config, verified.)
// ---------------------------------------------------------------------------
__global__ void __launch_bounds__(256) gemm1_tf32_kernel(const float* __restrict__ A,
                                                         const float* __restrict__ B,
                                                         const float* __restrict__ bias,
                                                         float* __restrict__ C) {
    constexpr int K = F_CAT, N = HIDDEN;
    constexpr int BK = 32;

    __shared__ float As[64][BK + 4];   // [row][k]
    __shared__ float Bs[BK][68];       // [k][col]

    const int bm   = blockIdx.y * 64;
    const int bn   = blockIdx.x * 64;
    const int tid  = threadIdx.x;
    const int wid  = tid >> 5;
    const int lane = tid & 31;
    const int gid  = lane >> 2;        // groupID 0..7
    const int tig  = lane & 3;         // thread-in-group 0..3
    const int wm   = (wid >> 1) * 16;  // warp m offset
    const int wn   = (wid & 1) * 32;   // warp n offset

    float d[4][4] = {};                // [ntile][reg]

    for (int k0 = 0; k0 < K; k0 += BK) {
        #pragma unroll
        for (int i = 0; i < 2; i++) {
            int idx  = tid + 256 * i;
            int row  = idx >> 3;
            int quad = idx & 7;
            float4 v = *(const float4*)(A + (size_t)(bm + row) * K + k0 + quad * 4);
            As[row][quad * 4 + 0] = to_tf32(v.x);
            As[row][quad * 4 + 1] = to_tf32(v.y);
            As[row][quad * 4 + 2] = to_tf32(v.z);
            As[row][quad * 4 + 3] = to_tf32(v.w);
        }
        #pragma unroll
        for (int i = 0; i < 2; i++) {
            int idx  = tid + 256 * i;
            int row  = idx >> 4;
            int quad = idx & 15;
            float4 v = *(const float4*)(B + (size_t)(k0 + row) * N + bn + quad * 4);
            Bs[row][quad * 4 + 0] = to_tf32(v.x);
            Bs[row][quad * 4 + 1] = to_tf32(v.y);
            Bs[row][quad * 4 + 2] = to_tf32(v.z);
            Bs[row][quad * 4 + 3] = to_tf32(v.w);
        }
        __syncthreads();

        #pragma unroll
        for (int ks = 0; ks < BK; ks += 8) {
            uint32_t a[4];
            {
                int r0 = wm + gid;
                a[0] = __float_as_uint(As[r0    ][ks + tig    ]);
                a[1] = __float_as_uint(As[r0 + 8][ks + tig    ]);
                a[2] = __float_as_uint(As[r0    ][ks + tig + 4]);
                a[3] = __float_as_uint(As[r0 + 8][ks + tig + 4]);
            }
            uint32_t b[4][2];
            #pragma unroll
            for (int nt = 0; nt < 4; nt++) {
                int c0 = wn + nt * 8 + gid;
                b[nt][0] = __float_as_uint(Bs[ks + tig    ][c0]);
                b[nt][1] = __float_as_uint(Bs[ks + tig + 4][c0]);
            }
            #pragma unroll
            for (int nt = 0; nt < 4; nt++)
                mma_tf32(d[nt], a[0], a[1], a[2], a[3], b[nt][0], b[nt][1]);
        }
        __syncthreads();
    }

    #pragma unroll
    for (int nt = 0; nt < 4; nt++) {
        int row = bm + wm + gid;
        int col = bn + wn + nt * 8 + tig * 2;
        float2 bv = *(const float2*)(bias + col);
        float2 o0 = {fmaxf(d[nt][0] + bv.x, 0.0f),
                     fmaxf(d[nt][1] + bv.y, 0.0f)};
        float2 o1 = {fmaxf(d[nt][2] + bv.x, 0.0f),
                     fmaxf(d[nt][3] + bv.y, 0.0f)};
        *(float2*)(C + (size_t)row       * N + col) = o0;
        *(float2*)(C + (size_t)(row + 8) * N + col) = o1;
    }
}

// ---------------------------------------------------------------------------
// 3) GEMM2 via tf32 tensor cores with 8-way warp split-K:
//    out = h @ W2 + b2.  M=1024, N=128, K=512.
//    32x32 out-tile (grid 4x32=128), 256 threads = 8 warps; per 64-wide
//    K-chunk each warp owns an 8-wide k-slice (kloc = wid*8); accumulators
//    carried in registers across 8 chunks; deterministic fixed-tree smem
//    reduction (4..7 -> 0..3, 2..3 -> 0..1, 1 -> 0) + bias in epilogue.
// ---------------------------------------------------------------------------
__global__ void __launch_bounds__(256) gemm2_tf32_kernel(const float* __restrict__ A,
                                                         const float* __restrict__ B,
                                                         const float* __restrict__ bias,
                                                         float* __restrict__ C) {
    constexpr int K = HIDDEN, N = F_OUT;
    constexpr int BM = 32, BN = 32, BKC = 64;

    __shared__ float As[BM][BKC + 4];      // [row][k]   32 x 68
    __shared__ float Bs[BKC][BN + 4];      // [k][col]   64 x 36
    __shared__ float red[4][BM][BN + 1];   // reduction staging

    const int bm   = blockIdx.y * BM;
    const int bn   = blockIdx.x * BN;
    const int tid  = threadIdx.x;
    const int wid  = tid >> 5;
    const int lane = tid & 31;
    const int gid  = lane >> 2;
    const int tig  = lane & 3;
    const int kloc = wid * 8;              // this warp's k-slice within chunk

    float d[2][4][4] = {};                 // [mtile][ntile][reg]

    for (int kc = 0; kc < K; kc += BKC) {
        // A tile 32x64: 512 float4 -> 2 per thread
        #pragma unroll
        for (int i = 0; i < 2; i++) {
            int idx  = tid + 256 * i;
            int row  = idx >> 4;           // 32 rows, 16 quads/row
            int quad = idx & 15;
            float4 v = *(const float4*)(A + (size_t)(bm + row) * K + kc + quad * 4);
            As[row][quad * 4 + 0] = to_tf32(v.x);
            As[row][quad * 4 + 1] = to_tf32(v.y);
            As[row][quad * 4 + 2] = to_tf32(v.z);
            As[row][quad * 4 + 3] = to_tf32(v.w);
        }
        // B tile 64x32: 512 float4 -> 2 per thread
        #pragma unroll
        for (int i = 0; i < 2; i++) {
            int idx  = tid + 256 * i;
            int row  = idx >> 3;           // 64 rows, 8 quads/row
            int quad = idx & 7;
            float4 v = *(const float4*)(B + (size_t)(kc + row) * N + bn + quad * 4);
            Bs[row][quad * 4 + 0] = to_tf32(v.x);
            Bs[row][quad * 4 + 1] = to_tf32(v.y);
            Bs[row][quad * 4 + 2] = to_tf32(v.z);
            Bs[row][quad * 4 + 3] = to_tf32(v.w);
        }
        __syncthreads();

        uint32_t a[2][4];
        #pragma unroll
        for (int mt = 0; mt < 2; mt++) {
            int r0 = mt * 16 + gid;
            a[mt][0] = __float_as_uint(As[r0    ][kloc + tig    ]);
            a[mt][1] = __float_as_uint(As[r0 + 8][kloc + tig    ]);
            a[mt][2] = __float_as_uint(As[r0    ][kloc + tig + 4]);
            a[mt][3] = __float_as_uint(As[r0 + 8][kloc + tig + 4]);
        }
        uint32_t b[4][2];
        #pragma unroll
        for (int nt = 0; nt < 4; nt++) {
            int c0 = nt * 8 + gid;
            b[nt][0] = __float_as_uint(Bs[kloc + tig    ][c0]);
            b[nt][1] = __float_as_uint(Bs[kloc + tig + 4][c0]);
        }
        #pragma unroll
        for (int mt = 0; mt < 2; mt++)
            #pragma unroll
            for (int nt = 0; nt < 4; nt++)
                mma_tf32(d[mt][nt], a[mt][0], a[mt][1], a[mt][2], a[mt][3],
                         b[nt][0], b[nt][1]);
        __syncthreads();
    }

    // Deterministic fixed-tree reduction over the 8 warp partials.
    // Register fragment (mt,nt): rows mt*16+gid (regs 0,1) and +8 (regs 2,3),
    // cols nt*8 + tig*2 (+1).
    #pragma unroll
    for (int step = 4; step > 0; step >>= 1) {
        if (wid >= step && wid < 2 * step) {
            #pragma unroll
            for (int mt = 0; mt < 2; mt++)
                #pragma unroll
                for (int nt = 0; nt < 4; nt++) {
                    int r0 = mt * 16 + gid, c0 = nt * 8 + tig * 2;
                    red[wid - step][r0    ][c0    ] = d[mt][nt][0];
                    red[wid - step][r0    ][c0 + 1] = d[mt][nt][1];
                    red[wid - step][r0 + 8][c0    ] = d[mt][nt][2];
                    red[wid - step][r0 + 8][c0 + 1] = d[mt][nt][3];
                }
        }
        __syncthreads();
        if (wid < step) {
            #pragma unroll
            for (int mt = 0; mt < 2; mt++)
                #pragma unroll
                for (int nt = 0; nt < 4; nt++) {
                    int r0 = mt * 16 + gid, c0 = nt * 8 + tig * 2;
                    d[mt][nt][0] += red[wid][r0    ][c0    ];
                    d[mt][nt][1] += red[wid][r0    ][c0 + 1];
                    d[mt][nt][2] += red[wid][r0 + 8][c0    ];
                    d[mt][nt][3] += red[wid][r0 + 8][c0 + 1];
                }
        }
        __syncthreads();
    }

    if (wid == 0) {
        #pragma unroll
        for (int mt = 0; mt < 2; mt++)
            #pragma unroll
            for (int nt = 0; nt < 4; nt++) {
                int row = bm + mt * 16 + gid;
                int col = bn + nt * 8 + tig * 2;
                float2 bv = *(const float2*)(bias + col);
                float2 o0 = {d[mt][nt][0] + bv.x, d[mt][nt][1] + bv.y};
                float2 o1 = {d[mt][nt][2] + bv.x, d[mt][nt][3] + bv.y};
                *(float2*)(C + (size_t)row       * N + col) = o0;
                *(float2*)(C + (size_t)(row + 8) * N + col) = o1;
            }
    }
}

// ---------------------------------------------------------------------------
// Launch. Inputs: x, edge_index, edge_attr, u, batch, W1, b1, W2, b2.
// edge_* unused; int64 inputs arrive as int32 on device.
// ---------------------------------------------------------------------------
extern "C" void kernel_launch(void* const* d_in, const int* in_sizes, int n_in,
                              void* d_out, int out_size) {
    const float* x     = (const float*)d_in[0];
    const float* u     = (const float*)d_in[3];
    const int*   batch = (const int*)d_in[4];
    const float* W1    = (const float*)d_in[5];
    const float* b1    = (const float*)d_in[6];
    const float* W2    = (const float*)d_in[7];
    const float* b2    = (const float*)d_in[8];
    float*       out   = (float*)d_out;

    void *p_concat = nullptr, *p_h = nullptr;
    cudaGetSymbolAddress(&p_concat, g_concat);
    cudaGetSymbolAddress(&p_h, g_h);

    // 1) segment mean + concat (warp-parallel bounds search), single wave
    seg_mean_kernel<<<N_GRAPHS, 256>>>(x, u, batch);

    // 2) h = relu(concat @ W1 + b1): tf32 tensor cores, 8 warps, grid 128
    gemm1_tf32_kernel<<<dim3(HIDDEN / 64, N_GRAPHS / 64), 256>>>(
        (const float*)p_concat, W1, b1, (float*)p_h);

    // 3) out = h @ W2 + b2: tf32 tensor cores, 8-way warp split-K, grid 128
    gemm2_tf32_kernel<<<dim3(F_OUT / 32, N_GRAPHS / 32), 256>>>(
        (const float*)p_h, W2, b2, out);
}

// round 17
// speedup vs baseline: 1.0053x; 1.0053x over previous
#include <cuda_runtime.h>
#include <cstdint>

#define N_NODES   1048576
#define N_GRAPHS  1024
#define F_X       128
#define F_U       128
#define F_CAT     256
#define HIDDEN    512
#define F_OUT     128

// Scratch (allocation-free rule: __device__ globals)
__device__ float g_concat[N_GRAPHS * F_CAT];   // [1024,256] = x_agg || u
__device__ float g_h[N_GRAPHS * HIDDEN];       // [1024,512]

// Dataflow sync state (zero-init at load; reset by mlp_kernel's tail barrier)
__device__ unsigned g_group_done[16];   // graphs done per 64-graph band
__device__ unsigned g_h_done[16];       // GEMM1 tiles done per 64-row band (8 each)
__device__ unsigned g_bar;              // monotonic end-barrier counter

// ---------------------------------------------------------------------------
// Warp-collective lower_bound on sorted int array: 32-ary search.
// ---------------------------------------------------------------------------
__device__ __forceinline__ int warp_lower_bound(const int* __restrict__ batch,
                                                int target, int lane) {
    int lo = 0, hi = N_NODES;              // answer in [lo, hi]
    while (hi - lo > 32) {
        int step = (hi - lo) >> 5;         // >= 1
        int pos  = lo + lane * step;
        int v    = __ldg(batch + pos);
        unsigned mask = __ballot_sync(0xffffffffu, v < target);
        if (mask == 0) {
            hi = lo + step;
        } else {
            int istar = 31 - __clz(mask);
            int nlo   = lo + istar * step;
            int nhi   = (istar < 31) ? (nlo + step) : hi;
            lo = nlo; hi = nhi;
        }
    }
    int pos = lo + lane;
    int v   = (pos < hi) ? __ldg(batch + pos) : 0x7fffffff;
    unsigned mask = __ballot_sync(0xffffffffu, (pos < hi) && (v < target));
    return lo + __popc(mask);
}

// ---------------------------------------------------------------------------
// 1) Segment mean of x -> g_concat[:,0:128]; u -> g_concat[:,128:256].
//    One block per graph, 256 threads; single wave; at the spr_max floor.
//    On completion, releases its 64-graph band counter for the MLP kernel.
// ---------------------------------------------------------------------------
__global__ void __launch_bounds__(256, 8) seg_mean_kernel(const float* __restrict__ x,
                                                          const float* __restrict__ u,
                                                          const int*   __restrict__ batch) {
    const int g    = blockIdx.x;
    const int tid  = threadIdx.x;
    const int lane = tid & 31;   // feature quad
    const int grp  = tid >> 5;   // row group 0..7

    __shared__ int s_se[2];
    if (grp < 2) {               // warp 0 -> start, warp 1 -> end
        int r = warp_lower_bound(batch, g + grp, lane);
        if (lane == 0) s_se[grp] = r;
    }
    __syncthreads();
    const int start = s_se[0];
    const int end   = s_se[1];

    const float* xb = x + (size_t)lane * 4;

    float4 a0 = {0,0,0,0}, a1 = {0,0,0,0};
    int r = start + grp;
    for (; r + 8 < end; r += 16) {      // 2 loads in flight per thread
        float4 v0 = __ldcs((const float4*)(xb + (size_t)(r    ) * F_X));
        float4 v1 = __ldcs((const float4*)(xb + (size_t)(r + 8) * F_X));
        a0.x += v0.x; a0.y += v0.y; a0.z += v0.z; a0.w += v0.w;
        a1.x += v1.x; a1.y += v1.y; a1.z += v1.z; a1.w += v1.w;
    }
    if (r < end) {
        float4 v = __ldcs((const float4*)(xb + (size_t)r * F_X));
        a0.x += v.x; a0.y += v.y; a0.z += v.z; a0.w += v.w;
    }
    a0.x += a1.x; a0.y += a1.y; a0.z += a1.z; a0.w += a1.w;

    __shared__ float4 sm[8][32];
    sm[grp][lane] = a0;
    __syncthreads();
    #pragma unroll
    for (int s = 4; s > 0; s >>= 1) {
        if (grp < s) {
            float4 a = sm[grp][lane];
            float4 b = sm[grp + s][lane];
            a.x += b.x; a.y += b.y; a.z += b.z; a.w += b.w;
            sm[grp][lane] = a;
        }
        __syncthreads();
    }

    if (grp == 0) {
        int cnt = end - start;
        float inv = (cnt > 0) ? (1.0f / (float)cnt) : 0.0f;
        float4 a = sm[0][lane];
        a.x *= inv; a.y *= inv; a.z *= inv; a.w *= inv;
        *(float4*)(g_concat + (size_t)g * F_CAT + lane * 4) = a;
    } else if (grp == 1) {
        float4 v = *(const float4*)(u + (size_t)g * F_U + lane * 4);
        *(float4*)(g_concat + (size_t)g * F_CAT + F_X + lane * 4) = v;
    }

    // Release this graph's band (release: fence before increment)
    __syncthreads();
    if (tid == 0) {
        __threadfence();
        atomicAdd(&g_group_done[g >> 6], 1u);
    }
}

// ---------------------------------------------------------------------------
// tf32 helpers
// ---------------------------------------------------------------------------
__device__ __forceinline__ float to_tf32(float f) {
    uint32_t u;
    asm("cvt.rna.tf32.f32 %0, %1;" : "=r"(u) : "f"(f));
    return __uint_as_float(u);
}

__device__ __forceinline__ void mma_tf32(float d[4],
                                         uint32_t a0, uint32_t a1, uint32_t a2, uint32_t a3,
                                         uint32_t b0, uint32_t b1) {
    asm("mma.sync.aligned.m16n8k8.row.col.f32.tf32.tf32.f32 "
        "{%0,%1,%2,%3}, {%4,%5,%6,%7}, {%8,%9}, {%0,%1,%2,%3};"
        : "+f"(d[0]), "+f"(d[1]), "+f"(d[2]), "+f"(d[3])
        : "r"(a0), "r"(a1), "r"(a2), "r"(a3), "r"(b0), "r"(b1));
}

__device__ __forceinline__ void spin_until_ge(volatile unsigned* p, unsigned v) {
    while (*p < v) __nanosleep(128);
}

// ---------------------------------------------------------------------------
// 2) Fused MLP, dataflow-synchronized with seg_mean. Grid 128, 256 threads.
//    Phase 1 (GEMM1, tf32): bid -> (m1 = bid>>3 of 16 bands, n1 = bid&7);
//      waits g_group_done[m1]==64, computes h = relu(concat@W1+b1) for its
//      64x64 tile, releases g_h_done[m1].
//    Phase 2 (GEMM2, tf32, 8-way warp split-K): bid -> (m2 = bid>>2, n2=bid&3);
//      waits g_h_done[m2>>1]==8, computes out tile 32x32.
//    Tail: monotonic barrier over the 128 blocks; last arriver resets counters.
//    Shared memory overlaid in one pool (34 KB).
// ---------------------------------------------------------------------------
__global__ void __launch_bounds__(256) mlp_kernel(const float* __restrict__ W1,
                                                  const float* __restrict__ b1,
                                                  const float* __restrict__ W2,
                                                  const float* __restrict__ b2,
                                                  float* __restrict__ out) {
    __shared__ float sp[8704];   // pool: phase1 4480 floats; phase2 8704 floats

    const int bid  = blockIdx.x;
    const int tid  = threadIdx.x;
    const int wid  = tid >> 5;
    const int lane = tid & 31;
    const int gid  = lane >> 2;        // mma groupID 0..7
    const int tig  = lane & 3;         // thread-in-group 0..3

    // ======================= Phase 1: GEMM1 64x64 tf32 =======================
    {
        const int m1 = bid >> 3;            // 16 m-bands of 64 rows
        const int n1 = bid & 7;             // 8 n-tiles of 64 cols
        const int bm = m1 * 64;
        const int bn = n1 * 64;

        // wait for this band's 64 graphs
        if (tid == 0) spin_until_ge(&g_group_done[m1], 64u);
        __syncthreads();
        __threadfence();                    // acquire

        // As1[64][36] at sp[0]; Bs1[32][68] at sp[2304]
        float* As1 = sp;
        float* Bs1 = sp + 2304;
        constexpr int K = F_CAT, N = HIDDEN, BK = 32;

        float d[4][4] = {};                 // [ntile][reg]
        const int wm = (wid >> 1) * 16;
        const int wn = (wid & 1) * 32;

        for (int k0 = 0; k0 < K; k0 += BK) {
            #pragma unroll
            for (int i = 0; i < 2; i++) {   // A 64x32
                int idx  = tid + 256 * i;
                int row  = idx >> 3;
                int quad = idx & 7;
                float4 v = *(const float4*)(g_concat + (size_t)(bm + row) * K + k0 + quad * 4);
                As1[row * 36 + quad * 4 + 0] = to_tf32(v.x);
                As1[row * 36 + quad * 4 + 1] = to_tf32(v.y);
                As1[row * 36 + quad * 4 + 2] = to_tf32(v.z);
                As1[row * 36 + quad * 4 + 3] = to_tf32(v.w);
            }
            #pragma unroll
            for (int i = 0; i < 2; i++) {   // B 32x64
                int idx  = tid + 256 * i;
                int row  = idx >> 4;
                int quad = idx & 15;
                float4 v = *(const float4*)(W1 + (size_t)(k0 + row) * N + bn + quad * 4);
                Bs1[row * 68 + quad * 4 + 0] = to_tf32(v.x);
                Bs1[row * 68 + quad * 4 + 1] = to_tf32(v.y);
                Bs1[row * 68 + quad * 4 + 2] = to_tf32(v.z);
                Bs1[row * 68 + quad * 4 + 3] = to_tf32(v.w);
            }
            __syncthreads();

            #pragma unroll
            for (int ks = 0; ks < BK; ks += 8) {
                uint32_t a[4];
                {
                    int r0 = wm + gid;
                    a[0] = __float_as_uint(As1[(r0    ) * 36 + ks + tig    ]);
                    a[1] = __float_as_uint(As1[(r0 + 8) * 36 + ks + tig    ]);
                    a[2] = __float_as_uint(As1[(r0    ) * 36 + ks + tig + 4]);
                    a[3] = __float_as_uint(As1[(r0 + 8) * 36 + ks + tig + 4]);
                }
                uint32_t b[4][2];
                #pragma unroll
                for (int nt = 0; nt < 4; nt++) {
                    int c0 = wn + nt * 8 + gid;
                    b[nt][0] = __float_as_uint(Bs1[(ks + tig    ) * 68 + c0]);
                    b[nt][1] = __float_as_uint(Bs1[(ks + tig + 4) * 68 + c0]);
                }
                #pragma unroll
                for (int nt = 0; nt < 4; nt++)
                    mma_tf32(d[nt], a[0], a[1], a[2], a[3], b[nt][0], b[nt][1]);
            }
            __syncthreads();
        }

        #pragma unroll
        for (int nt = 0; nt < 4; nt++) {    // bias + relu -> g_h
            int row = bm + wm + gid;
            int col = bn + wn + nt * 8 + tig * 2;
            float2 bv = *(const float2*)(b1 + col);
            float2 o0 = {fmaxf(d[nt][0] + bv.x, 0.0f), fmaxf(d[nt][1] + bv.y, 0.0f)};
            float2 o1 = {fmaxf(d[nt][2] + bv.x, 0.0f), fmaxf(d[nt][3] + bv.y, 0.0f)};
            *(float2*)(g_h + (size_t)row       * N + col) = o0;
            *(float2*)(g_h + (size_t)(row + 8) * N + col) = o1;
        }

        __syncthreads();
        if (tid == 0) {
            __threadfence();
            atomicAdd(&g_h_done[m1], 1u);
        }
    }

    // =============== Phase 2: GEMM2 32x32 tf32, 8-way split-K ===============
    {
        const int m2 = bid >> 2;            // 32 m-bands of 32 rows
        const int n2 = bid & 3;             // 4 n-tiles of 32 cols
        const int bm = m2 * 32;
        const int bn = n2 * 32;

        // wait for the 8 GEMM1 tiles covering h rows [m2*32, m2*32+32)
        if (tid == 0) spin_until_ge(&g_h_done[m2 >> 1], 8u);
        __syncthreads();
        __threadfence();                    // acquire

        // As2[32][68] at sp[0]; Bs2[64][36] at sp[2176]; red[4][32][33] at sp[4480]
        float* As2 = sp;
        float* Bs2 = sp + 2176;
        float* red = sp + 4480;
        constexpr int K = HIDDEN, N = F_OUT, BKC = 64;
        const int kloc = wid * 8;

        float d[2][4][4] = {};

        for (int kc = 0; kc < K; kc += BKC) {
            #pragma unroll
            for (int i = 0; i < 2; i++) {   // A 32x64
                int idx  = tid + 256 * i;
                int row  = idx >> 4;
                int quad = idx & 15;
                float4 v = *(const float4*)(g_h + (size_t)(bm + row) * K + kc + quad * 4);
                As2[row * 68 + quad * 4 + 0] = to_tf32(v.x);
                As2[row * 68 + quad * 4 + 1] = to_tf32(v.y);
                As2[row * 68 + quad * 4 + 2] = to_tf32(v.z);
                As2[row * 68 + quad * 4 + 3] = to_tf32(v.w);
            }
            #pragma unroll
            for (int i = 0; i < 2; i++) {   // B 64x32
                int idx  = tid + 256 * i;
                int row  = idx >> 3;
                int quad = idx & 7;
                float4 v = *(const float4*)(W2 + (size_t)(kc + row) * N + bn + quad * 4);
                Bs2[row * 36 + quad * 4 + 0] = to_tf32(v.x);
                Bs2[row * 36 + quad * 4 + 1] = to_tf32(v.y);
                Bs2[row * 36 + quad * 4 + 2] = to_tf32(v.z);
                Bs2[row * 36 + quad * 4 + 3] = to_tf32(v.w);
            }
            __syncthreads();

            uint32_t a[2][4];
            #pragma unroll
            for (int mt = 0; mt < 2; mt++) {
                int r0 = mt * 16 + gid;
                a[mt][0] = __float_as_uint(As2[(r0    ) * 68 + kloc + tig    ]);
                a[mt][1] = __float_as_uint(As2[(r0 + 8) * 68 + kloc + tig    ]);
                a[mt][2] = __float_as_uint(As2[(r0    ) * 68 + kloc + tig + 4]);
                a[mt][3] = __float_as_uint(As2[(r0 + 8) * 68 + kloc + tig + 4]);
            }
            uint32_t b[4][2];
            #pragma unroll
            for (int nt = 0; nt < 4; nt++) {
                int c0 = nt * 8 + gid;
                b[nt][0] = __float_as_uint(Bs2[(kloc + tig    ) * 36 + c0]);
                b[nt][1] = __float_as_uint(Bs2[(kloc + tig + 4) * 36 + c0]);
            }
            #pragma unroll
            for (int mt = 0; mt < 2; mt++)
                #pragma unroll
                for (int nt = 0; nt < 4; nt++)
                    mma_tf32(d[mt][nt], a[mt][0], a[mt][1], a[mt][2], a[mt][3],
                             b[nt][0], b[nt][1]);
            __syncthreads();
        }

        // Deterministic fixed-tree reduction over the 8 warp partials.
        #pragma unroll
        for (int step = 4; step > 0; step >>= 1) {
            if (wid >= step && wid < 2 * step) {
                #pragma unroll
                for (int mt = 0; mt < 2; mt++)
                    #pragma unroll
                    for (int nt = 0; nt < 4; nt++) {
                        int r0 = mt * 16 + gid, c0 = nt * 8 + tig * 2;
                        float* rw = red + (size_t)(wid - step) * (32 * 33);
                        rw[(r0    ) * 33 + c0    ] = d[mt][nt][0];
                        rw[(r0    ) * 33 + c0 + 1] = d[mt][nt][1];
                        rw[(r0 + 8) * 33 + c0    ] = d[mt][nt][2];
                        rw[(r0 + 8) * 33 + c0 + 1] = d[mt][nt][3];
                    }
            }
            __syncthreads();
            if (wid < step) {
                #pragma unroll
                for (int mt = 0; mt < 2; mt++)
                    #pragma unroll
                    for (int nt = 0; nt < 4; nt++) {
                        int r0 = mt * 16 + gid, c0 = nt * 8 + tig * 2;
                        float* rw = red + (size_t)wid * (32 * 33);
                        d[mt][nt][0] += rw[(r0    ) * 33 + c0    ];
                        d[mt][nt][1] += rw[(r0    ) * 33 + c0 + 1];
                        d[mt][nt][2] += rw[(r0 + 8) * 33 + c0    ];
                        d[mt][nt][3] += rw[(r0 + 8) * 33 + c0 + 1];
                    }
            }
            __syncthreads();
        }

        if (wid == 0) {
            #pragma unroll
            for (int mt = 0; mt < 2; mt++)
                #pragma unroll
                for (int nt = 0; nt < 4; nt++) {
                    int row = bm + mt * 16 + gid;
                    int col = bn + nt * 8 + tig * 2;
                    float2 bv = *(const float2*)(b2 + col);
                    float2 o0 = {d[mt][nt][0] + bv.x, d[mt][nt][1] + bv.y};
                    float2 o1 = {d[mt][nt][2] + bv.x, d[mt][nt][3] + bv.y};
                    *(float2*)(out + (size_t)row       * N + col) = o0;
                    *(float2*)(out + (size_t)(row + 8) * N + col) = o1;
                }
        }
    }

    // ===== Tail: monotonic barrier over 128 blocks; last arriver resets =====
    __syncthreads();
    if (tid == 0) {
        unsigned token = atomicAdd(&g_bar, 1u);
        unsigned target = ((token >> 7) + 1u) << 7;   // next multiple of 128
        spin_until_ge(&g_bar, target);
        if (token == target - 1u) {                   // last arriver resets
            #pragma unroll
            for (int i = 0; i < 16; i++) {
                g_group_done[i] = 0u;
                g_h_done[i]     = 0u;
            }
            __threadfence();
        }
    }
}

// ---------------------------------------------------------------------------
// Launch. Inputs: x, edge_index, edge_attr, u, batch, W1, b1, W2, b2.
// edge_* unused; int64 inputs arrive as int32 on device.
// mlp_kernel is launched back-to-back with seg_mean; it self-synchronizes on
// per-band done-counters, overlapping with seg_mean's retirement tail.
// ---------------------------------------------------------------------------
extern "C" void kernel_launch(void* const* d_in, const int* in_sizes, int n_in,
                              void* d_out, int out_size) {
    const float* x     = (const float*)d_in[0];
    const float* u     = (const float*)d_in[3];
    const int*   batch = (const int*)d_in[4];
    const float* W1    = (const float*)d_in[5];
    const float* b1    = (const float*)d_in[6];
    const float* W2    = (const float*)d_in[7];
    const float* b2    = (const float*)d_in[8];
    float*       out   = (float*)d_out;

    seg_mean_kernel<<<N_GRAPHS, 256>>>(x, u, batch);
    mlp_kernel<<<128, 256>>>(W1, b1, W2, b2, out);
}